// round 1
// baseline (speedup 1.0000x reference)
#include <cuda_runtime.h>
#include <cstdint>

#define B_ 2
#define H_ 12
#define S_ 256
#define E_ 64
#define D_ 768        // H_*E_
#define L_ 25
#define LP_ 13        // label pairs (padded to 26)
#define WSTR 26       // W_s row stride (l dim, padded)
#define KT 16         // k-tile width
#define YSTR 18       // Y_s row stride (k dim, padded)
#define GROUPS 4      // (b,sk) groups per block
#define TPG 64        // threads per group

// Transposed attention probs: g_pt[b,h,sk,sq] = p[b,h,sq,sk]
__device__ float g_pt[B_ * H_ * S_ * S_];

__global__ void transpose_p_kernel(const float* __restrict__ p) {
    __shared__ float tile[32][33];
    int bh = blockIdx.z;                 // 0..23
    int x0 = blockIdx.x * 32;            // sk tile origin in source (inner dim)
    int y0 = blockIdx.y * 32;            // sq tile origin in source (outer dim)
    int tx = threadIdx.x;                // 0..31
    int ty = threadIdx.y;                // 0..7
    const float* src = p + (size_t)bh * (S_ * S_);
#pragma unroll
    for (int j = 0; j < 32; j += 8)
        tile[ty + j][tx] = src[(size_t)(y0 + ty + j) * S_ + (x0 + tx)];
    __syncthreads();
    float* dst = g_pt + (size_t)bh * (S_ * S_);
#pragma unroll
    for (int j = 0; j < 32; j += 8)
        dst[(size_t)(x0 + ty + j) * S_ + (y0 + tx)] = tile[tx][ty + j];
}

__device__ __forceinline__ unsigned long long pack_dup(float x) {
    unsigned long long r;
    unsigned u = __float_as_uint(x);
    asm("mov.b64 %0, {%1, %1};" : "=l"(r) : "r"(u));
    return r;
}

__device__ __forceinline__ void fma2(unsigned long long& acc,
                                     unsigned long long a,
                                     unsigned long long b) {
    asm("fma.rn.f32x2 %0, %1, %2, %0;" : "+l"(acc) : "l"(a), "l"(b));
}

__global__ void __launch_bounds__(256, 1) mhs_main_kernel(
    const float* __restrict__ v,     // [B,H,S,E]
    const float* __restrict__ rel,   // [B,S,S,768]
    const float* __restrict__ W,     // [25,768]
    const float* __restrict__ bias,  // [25]
    float* __restrict__ out)         // [B,S,25,S]
{
    extern __shared__ float smem[];
    // Layout: W_s [768][26] | Y_s [4 groups][256][18] | v_s [4 groups][768]
    float* W_s = smem;                                       // 19968 floats
    const int g2 = threadIdx.x >> 6;                         // group 0..3
    const int t  = threadIdx.x & 63;                         // thread in group
    float* Y_s = smem + D_ * WSTR + g2 * (S_ * YSTR);
    float* v_s = smem + D_ * WSTR + GROUPS * (S_ * YSTR) + g2 * D_;

    const int g  = blockIdx.x * GROUPS + g2;                 // 0..511
    const int b  = g >> 8;
    const int sk = g & 255;

    // Stage W transposed into smem: W_s[k*26 + l] = W[l*768 + k], pad l=25 with 0
    for (int idx = threadIdx.x; idx < L_ * D_; idx += 256) {
        int l = idx / D_;
        int k = idx - l * D_;
        W_s[k * WSTR + l] = W[idx];
    }
    for (int k = threadIdx.x; k < D_; k += 256)
        W_s[k * WSTR + 25] = 0.0f;

    // Stage v slice for this (b,sk): v_s[h*64+e]
    for (int j = t; j < D_; j += TPG) {
        int h = j >> 6;
        int e = j & 63;
        v_s[j] = v[(((size_t)b * H_ + h) * S_ + sk) * E_ + e];
    }

    __syncthreads();

    unsigned long long acc[LP_][4];
#pragma unroll
    for (int lp = 0; lp < LP_; ++lp)
#pragma unroll
        for (int q = 0; q < 4; ++q) acc[lp][q] = 0ull;

    const float* relb = rel + (size_t)b * S_ * S_ * D_ + (size_t)sk * D_;

    for (int tl = 0; tl < D_ / KT; ++tl) {
        const int k0 = tl * KT;
        const int h  = k0 >> 6;                 // constant within tile (16 | 64)
        const float* ptrow = g_pt + (((size_t)b * H_ + h) * S_ + sk) * S_;

        // Producer: build Y_s[row][k] = p[h,row] * (v[k] + rel[row,k])
#pragma unroll
        for (int i = 0; i < 16; ++i) {
            int idx = i * TPG + t;
            int row = idx >> 2;
            int c   = (idx & 3) * 4;
            const float4 r4 =
                *reinterpret_cast<const float4*>(relb + (size_t)row * (S_ * D_) + k0 + c);
            float  pv = ptrow[row];
            float4 v4 = *reinterpret_cast<const float4*>(v_s + k0 + c);
            float* yd = Y_s + row * YSTR + c;
            yd[0] = pv * (r4.x + v4.x);
            yd[1] = pv * (r4.y + v4.y);
            yd[2] = pv * (r4.z + v4.z);
            yd[3] = pv * (r4.w + v4.w);
        }
        __syncthreads();

        // Consumer: rank-1 updates, FFMA2 paired over l
#pragma unroll
        for (int kk = 0; kk < KT; ++kk) {
            unsigned long long y0 = pack_dup(Y_s[(t      ) * YSTR + kk]);
            unsigned long long y1 = pack_dup(Y_s[(t +  64) * YSTR + kk]);
            unsigned long long y2 = pack_dup(Y_s[(t + 128) * YSTR + kk]);
            unsigned long long y3 = pack_dup(Y_s[(t + 192) * YSTR + kk]);
            const float* wrow = W_s + (k0 + kk) * WSTR;
#pragma unroll
            for (int lp = 0; lp < LP_; ++lp) {
                unsigned long long w2 =
                    *reinterpret_cast<const unsigned long long*>(wrow + lp * 2);
                fma2(acc[lp][0], y0, w2);
                fma2(acc[lp][1], y1, w2);
                fma2(acc[lp][2], y2, w2);
                fma2(acc[lp][3], y3, w2);
            }
        }
        __syncthreads();
    }

    // Epilogue: add bias, write out[b][sk][l][sq] (sq coalesced across lanes)
    float* outb = out + (((size_t)b * S_ + sk) * L_) * S_;
#pragma unroll
    for (int lp = 0; lp < LP_; ++lp) {
        int l0 = lp * 2;
        float bb0 = bias[l0];
        float bb1 = (l0 + 1 < L_) ? bias[l0 + 1] : 0.0f;
#pragma unroll
        for (int q = 0; q < 4; ++q) {
            unsigned lo = (unsigned)(acc[lp][q] & 0xffffffffull);
            unsigned hi = (unsigned)(acc[lp][q] >> 32);
            int sq = t + q * 64;
            outb[(size_t)l0 * S_ + sq] = __uint_as_float(lo) + bb0;
            if (l0 + 1 < L_)
                outb[(size_t)(l0 + 1) * S_ + sq] = __uint_as_float(hi) + bb1;
        }
    }
}

extern "C" void kernel_launch(void* const* d_in, const int* in_sizes, int n_in,
                              void* d_out, int out_size) {
    const float* p    = (const float*)d_in[0];   // attention_probs [B,H,S,S]
    const float* v    = (const float*)d_in[1];   // value_attentions [B,H,S,E]
    const float* rel  = (const float*)d_in[2];   // relative_positions [B,S,S,768]
    const float* W    = (const float*)d_in[3];   // [25,768]
    const float* bias = (const float*)d_in[4];   // [25]
    float* out = (float*)d_out;                  // [B,S,25,S] fp32

    dim3 gt(S_ / 32, S_ / 32, B_ * H_);
    transpose_p_kernel<<<gt, dim3(32, 8)>>>(p);

    const int smem_bytes =
        (D_ * WSTR + GROUPS * S_ * YSTR + GROUPS * D_) * (int)sizeof(float); // 165888
    cudaFuncSetAttribute(mhs_main_kernel,
                         cudaFuncAttributeMaxDynamicSharedMemorySize, smem_bytes);
    mhs_main_kernel<<<(B_ * S_) / GROUPS, 256, smem_bytes>>>(v, rel, W, bias, out);
}

// round 2
// speedup vs baseline: 1.1705x; 1.1705x over previous
#include <cuda_runtime.h>
#include <cstdint>

#define B_ 2
#define H_ 12
#define S_ 256
#define E_ 64
#define D_ 768
#define L_ 25
#define LP_ 13
#define WSTR 26
#define KT 8          // k-tile width
#define NT 96         // D_/KT
#define RSTR 10       // rel-tile row stride (floats), gcd(10,32)=2
#define GROUPS 4
#define TPG 64
#define RS (S_ * D_)  // rel row (sq) stride in floats

typedef unsigned long long u64;

// Transposed attention probs: g_pt[b,h,sk,sq] = p[b,h,sq,sk]
__device__ float g_pt[B_ * H_ * S_ * S_];

__global__ void transpose_p_kernel(const float* __restrict__ p) {
    __shared__ float tile[32][33];
    int bh = blockIdx.z;
    int x0 = blockIdx.x * 32;
    int y0 = blockIdx.y * 32;
    int tx = threadIdx.x;
    int ty = threadIdx.y;
    const float* src = p + (size_t)bh * (S_ * S_);
#pragma unroll
    for (int j = 0; j < 32; j += 8)
        tile[ty + j][tx] = src[(size_t)(y0 + ty + j) * S_ + (x0 + tx)];
    __syncthreads();
    float* dst = g_pt + (size_t)bh * (S_ * S_);
#pragma unroll
    for (int j = 0; j < 32; j += 8)
        dst[(size_t)(x0 + ty + j) * S_ + (y0 + tx)] = tile[tx][ty + j];
}

__device__ __forceinline__ u64 pack_dup(unsigned u) {
    u64 r;
    asm("mov.b64 %0, {%1, %1};" : "=l"(r) : "r"(u));
    return r;
}
__device__ __forceinline__ u64 dupf(float x) { return pack_dup(__float_as_uint(x)); }

__device__ __forceinline__ void fma2(u64& acc, u64 a, u64 b) {
    asm("fma.rn.f32x2 %0, %1, %2, %0;" : "+l"(acc) : "l"(a), "l"(b));
}
__device__ __forceinline__ u64 add2(u64 a, u64 b) {
    u64 r; asm("add.rn.f32x2 %0, %1, %2;" : "=l"(r) : "l"(a), "l"(b)); return r;
}
__device__ __forceinline__ u64 mul2(u64 a, u64 b) {
    u64 r; asm("mul.rn.f32x2 %0, %1, %2;" : "=l"(r) : "l"(a), "l"(b)); return r;
}
__device__ __forceinline__ void unpack2(u64 x, unsigned& lo, unsigned& hi) {
    asm("mov.b64 {%0, %1}, %2;" : "=r"(lo), "=r"(hi) : "l"(x));
}

__device__ __forceinline__ void cpasync8(unsigned dst, const float* src) {
    asm volatile("cp.async.ca.shared.global [%0], [%1], 8;\n" :: "r"(dst), "l"(src));
}
__device__ __forceinline__ void cp_commit() {
    asm volatile("cp.async.commit_group;\n" ::: "memory");
}
__device__ __forceinline__ void cp_wait1() {
    asm volatile("cp.async.wait_group 1;\n" ::: "memory");
}
__device__ __forceinline__ void cp_wait0() {
    asm volatile("cp.async.wait_group 0;\n" ::: "memory");
}
__device__ __forceinline__ void gbar(int id) {
    asm volatile("bar.sync %0, 64;" :: "r"(id) : "memory");
}
__device__ __forceinline__ unsigned smem_u32(const void* p) {
    unsigned r;
    asm("{ .reg .u64 t; cvta.to.shared.u64 t, %1; cvt.u32.u64 %0, t; }" : "=r"(r) : "l"(p));
    return r;
}

__global__ void __launch_bounds__(256) mhs_main_kernel(
    const float* __restrict__ v,     // [B,H,S,E]
    const float* __restrict__ rel,   // [B,S,S,768]
    const float* __restrict__ W,     // [25,768]
    const float* __restrict__ bias,  // [25]
    float* __restrict__ out)         // [B,S,25,S]
{
    extern __shared__ float smem[];
    // Layout (floats): W_s[768*26] | R[4 groups][2 bufs][256*10] | v_s[4][768]
    float* W_s = smem;
    const int g2 = threadIdx.x >> 6;
    const int t  = threadIdx.x & 63;
    float* R0  = smem + D_ * WSTR + (g2 * 2    ) * (S_ * RSTR);
    float* R1  = smem + D_ * WSTR + (g2 * 2 + 1) * (S_ * RSTR);
    float* v_s = smem + D_ * WSTR + GROUPS * 2 * (S_ * RSTR) + g2 * D_;

    const int g  = blockIdx.x * GROUPS + g2;
    const int b  = g >> 8;
    const int sk = g & 255;

    const float* relb = rel + (size_t)b * S_ * S_ * D_ + (size_t)sk * D_;

    // Per-thread copy lane mapping: row base + fixed 8-byte column
    const int rb = t >> 2;            // 0..15
    const int jc = (t & 3) * 2;       // float column 0,2,4,6
    const unsigned R0u = smem_u32(R0) + (unsigned)(rb * RSTR + jc) * 4u;
    const unsigned R1u = smem_u32(R1) + (unsigned)(rb * RSTR + jc) * 4u;

    // Prefetch tile 0 into R0 (async, overlaps W/v staging)
    {
        const float* src = relb + (size_t)rb * RS + jc;
#pragma unroll
        for (int i = 0; i < 16; ++i) {
            cpasync8(R0u + (unsigned)(i * 16 * RSTR) * 4u, src);
            src += (size_t)16 * RS;
        }
        cp_commit();
    }

    // Stage W transposed: W_s[k*26 + l] = W[l*768 + k]
    for (int idx = threadIdx.x; idx < L_ * D_; idx += 256) {
        int l = idx / D_;
        int k = idx - l * D_;
        W_s[k * WSTR + l] = W[idx];
    }
    for (int k = threadIdx.x; k < D_; k += 256)
        W_s[k * WSTR + 25] = 0.0f;

    // Stage v slice
    for (int j = t; j < D_; j += TPG) {
        int h = j >> 6;
        int e = j & 63;
        v_s[j] = v[(((size_t)b * H_ + h) * S_ + sk) * E_ + e];
    }

    // Prefetch pv for h=0
    const float* ptb = g_pt + (((size_t)b * H_) * S_ + sk) * S_;  // h=0 row
    float pvf[4];
#pragma unroll
    for (int q = 0; q < 4; ++q) pvf[q] = __ldg(ptb + t + q * 64);

    __syncthreads();

    u64 acc[LP_][4];
#pragma unroll
    for (int lp = 0; lp < LP_; ++lp)
#pragma unroll
        for (int q = 0; q < 4; ++q) acc[lp][q] = 0ull;

    u64 pv2[4];
    const int barid = g2 + 1;

    for (int tl = 0; tl < NT; ++tl) {
        const int k0 = tl * KT;

        if ((tl & 7) == 0) {  // new h block: use prefetched pv
#pragma unroll
            for (int q = 0; q < 4; ++q) pv2[q] = dupf(pvf[q]);
        }

        // Issue async copy of next tile
        if (tl + 1 < NT) {
            const unsigned dst = ((tl + 1) & 1) ? R1u : R0u;
            const float* src = relb + (size_t)rb * RS + (k0 + KT) + jc;
#pragma unroll
            for (int i = 0; i < 16; ++i) {
                cpasync8(dst + (unsigned)(i * 16 * RSTR) * 4u, src);
                src += (size_t)16 * RS;
            }
            cp_commit();
            cp_wait1();   // current tile's copy complete
        } else {
            cp_wait0();
        }
        gbar(barid);      // whole group sees current buffer

        // Prefetch pv for next h block (overlaps consume)
        if ((tl & 7) == 7 && tl + 1 < NT) {
            const int hn = (tl + 1) >> 3;
            const float* ptr = g_pt + (((size_t)b * H_ + hn) * S_ + sk) * S_;
#pragma unroll
            for (int q = 0; q < 4; ++q) pvf[q] = __ldg(ptr + t + q * 64);
        }

        // Consume: y = pv*(v+rel), FFMA2 rank-1 updates paired over l
        const float* Rb = (tl & 1) ? R1 : R0;
#pragma unroll
        for (int p = 0; p < 4; ++p) {           // kk pairs
            const u64 v2 = *reinterpret_cast<const u64*>(v_s + k0 + 2 * p);
            u64 ydl[4], ydh[4];
#pragma unroll
            for (int q = 0; q < 4; ++q) {
                const u64 r2 =
                    *reinterpret_cast<const u64*>(Rb + (t + q * 64) * RSTR + 2 * p);
                const u64 y2 = mul2(add2(r2, v2), pv2[q]);
                unsigned lo, hi;
                unpack2(y2, lo, hi);
                ydl[q] = pack_dup(lo);
                ydh[q] = pack_dup(hi);
            }
            const float* w0 = W_s + (size_t)(k0 + 2 * p) * WSTR;
            const float* w1 = w0 + WSTR;
#pragma unroll
            for (int lp = 0; lp < LP_; ++lp) {
                const u64 wa = *reinterpret_cast<const u64*>(w0 + lp * 2);
                const u64 wb = *reinterpret_cast<const u64*>(w1 + lp * 2);
                fma2(acc[lp][0], ydl[0], wa);
                fma2(acc[lp][1], ydl[1], wa);
                fma2(acc[lp][2], ydl[2], wa);
                fma2(acc[lp][3], ydl[3], wa);
                fma2(acc[lp][0], ydh[0], wb);
                fma2(acc[lp][1], ydh[1], wb);
                fma2(acc[lp][2], ydh[2], wb);
                fma2(acc[lp][3], ydh[3], wb);
            }
        }
        gbar(barid);      // buffer (tl&1) free for reuse at tl+2
    }

    // Epilogue: bias + store out[b][sk][l][sq]
    float* outb = out + (((size_t)b * S_ + sk) * L_) * S_;
#pragma unroll
    for (int lp = 0; lp < LP_; ++lp) {
        int l0 = lp * 2;
        float bb0 = bias[l0];
        float bb1 = (l0 + 1 < L_) ? bias[l0 + 1] : 0.0f;
#pragma unroll
        for (int q = 0; q < 4; ++q) {
            unsigned lo, hi;
            unpack2(acc[lp][q], lo, hi);
            int sq = t + q * 64;
            outb[(size_t)l0 * S_ + sq] = __uint_as_float(lo) + bb0;
            if (l0 + 1 < L_)
                outb[(size_t)(l0 + 1) * S_ + sq] = __uint_as_float(hi) + bb1;
        }
    }
}

extern "C" void kernel_launch(void* const* d_in, const int* in_sizes, int n_in,
                              void* d_out, int out_size) {
    const float* p    = (const float*)d_in[0];
    const float* v    = (const float*)d_in[1];
    const float* rel  = (const float*)d_in[2];
    const float* W    = (const float*)d_in[3];
    const float* bias = (const float*)d_in[4];
    float* out = (float*)d_out;

    dim3 gt(S_ / 32, S_ / 32, B_ * H_);
    transpose_p_kernel<<<gt, dim3(32, 8)>>>(p);

    const int smem_bytes =
        (D_ * WSTR + GROUPS * 2 * S_ * RSTR + GROUPS * D_) * (int)sizeof(float); // 174080
    cudaFuncSetAttribute(mhs_main_kernel,
                         cudaFuncAttributeMaxDynamicSharedMemorySize, smem_bytes);
    mhs_main_kernel<<<(B_ * S_) / GROUPS, 256, smem_bytes>>>(v, rel, W, bias, out);
}

// round 4
// speedup vs baseline: 1.6042x; 1.3706x over previous
#include <cuda_runtime.h>
#include <cuda_bf16.h>
#include <cstdint>

#define B_ 2
#define H_ 12
#define S_ 256
#define E_ 64
#define D_ 768
#define L_ 25
#define RS (S_ * D_)      // rel sq-stride (floats)
#define NCHUNK 48         // k16 chunks

typedef unsigned long long u64;
typedef unsigned int u32;

// ---- smem layout (float offsets) ----
#define OFF_WS   0         // W packed frags: 2 dtypes x 48 x 32 x 8 u32 = 24576
#define OFF_RAW  24576     // 8 warps x 4 bufs x 32 rows x 24 floats = 24576
#define OFF_PS   49152     // 12 x 256
#define OFF_VS   52224     // 768
#define OFF_CVS  52992     // 25*12 = 300
#define OFF_BIAS 53296     // 32
#define SMEM_FLOATS 53328  // 213312 bytes

#define WPN (48 * 32 * 8)  // u32 per dtype

__device__ float g_pt[B_ * H_ * S_ * S_];
__device__ u32   g_wp[2 * WPN];

__global__ void transpose_p_kernel(const float* __restrict__ p) {
    __shared__ float tile[32][33];
    int bh = blockIdx.z, x0 = blockIdx.x * 32, y0 = blockIdx.y * 32;
    int tx = threadIdx.x, ty = threadIdx.y;
    const float* src = p + (size_t)bh * (S_ * S_);
#pragma unroll
    for (int j = 0; j < 32; j += 8)
        tile[ty + j][tx] = src[(size_t)(y0 + ty + j) * S_ + (x0 + tx)];
    __syncthreads();
    float* dst = g_pt + (size_t)bh * (S_ * S_);
#pragma unroll
    for (int j = 0; j < 32; j += 8)
        dst[(size_t)(x0 + ty + j) * S_ + (y0 + tx)] = tile[tx][ty + j];
}

// split two f32 into bf16x2 hi + bf16x2 lo (x0 -> low 16 bits = first k)
__device__ __forceinline__ void split_pair(float x0, float x1, u32& hi2, u32& lo2) {
    asm("cvt.rn.bf16x2.f32 %0, %1, %2;" : "=r"(hi2) : "f"(x1), "f"(x0));
    float h0 = __uint_as_float(hi2 << 16);
    float h1 = __uint_as_float(hi2 & 0xffff0000u);
    asm("cvt.rn.bf16x2.f32 %0, %1, %2;" : "=r"(lo2) : "f"(x1 - h1), "f"(x0 - h0));
}

// Pack W into mma B-fragment layout: g_wp[d][s][n][tg][j], j=0:k=16s+2tg, j=1:+8
__global__ void pack_w_kernel(const float* __restrict__ W) {
    int t = blockIdx.x * 256 + threadIdx.x;       // 0..6143
    if (t >= 48 * 32 * 4) return;
    int s = t >> 7, r = t & 127;
    int n = r >> 2, tg = r & 3;
#pragma unroll
    for (int j = 0; j < 2; ++j) {
        int k = 16 * s + 2 * tg + 8 * j;
        float w0 = (n < L_) ? W[n * D_ + k] : 0.0f;
        float w1 = (n < L_) ? W[n * D_ + k + 1] : 0.0f;
        u32 hi2, lo2;
        split_pair(w0, w1, hi2, lo2);
        int idx = (s * 32 + n) * 8 + tg * 2 + j;
        g_wp[idx] = hi2;
        g_wp[WPN + idx] = lo2;
    }
}

__device__ __forceinline__ void cpasync16(u32 dst, const float* src) {
    asm volatile("cp.async.cg.shared.global [%0], [%1], 16;\n" :: "r"(dst), "l"(src));
}
__device__ __forceinline__ void cp_commit() {
    asm volatile("cp.async.commit_group;\n" ::: "memory");
}
__device__ __forceinline__ void cp_wait3() {
    asm volatile("cp.async.wait_group 3;\n" ::: "memory");
}
__device__ __forceinline__ u32 smem_u32(const void* p) {
    u32 r;
    asm("{ .reg .u64 t; cvta.to.shared.u64 t, %1; cvt.u32.u64 %0, t; }" : "=r"(r) : "l"(p));
    return r;
}
__device__ __forceinline__ void mma_bf16(float* c, const u32* a, u32 b0, u32 b1) {
    asm volatile(
        "mma.sync.aligned.m16n8k16.row.col.f32.bf16.bf16.f32 "
        "{%0,%1,%2,%3}, {%4,%5,%6,%7}, {%8,%9}, {%0,%1,%2,%3};"
        : "+f"(c[0]), "+f"(c[1]), "+f"(c[2]), "+f"(c[3])
        : "r"(a[0]), "r"(a[1]), "r"(a[2]), "r"(a[3]), "r"(b0), "r"(b1));
}

__global__ void __launch_bounds__(256, 1) mhs_mma_kernel(
    const float* __restrict__ v,     // [B,H,S,E]
    const float* __restrict__ rel,   // [B,S,S,768]
    const float* __restrict__ W,     // [25,768] fp32
    const float* __restrict__ bias,  // [25]
    float* __restrict__ out)         // [B,S,25,S]
{
    extern __shared__ float smem[];
    const int tid  = threadIdx.x;
    const int w    = tid >> 5;           // warp 0..7, owns sq rows 32w..32w+31
    const int lane = tid & 31;
    const int g    = lane >> 2;          // groupID
    const int tg   = lane & 3;           // thread-in-group

    const int blk = blockIdx.x;
    const int b   = blk >> 8;
    const int sk  = blk & 255;

    float* p_s    = smem + OFF_PS;
    float* v_s    = smem + OFF_VS;
    float* cv_s   = smem + OFF_CVS;
    float* bias_s = smem + OFF_BIAS;
    float* rawb   = smem + OFF_RAW + w * (4 * 768);   // 4 bufs x 768 floats
    const u32 raw_su = smem_u32(rawb);
    const u32* wsh = (const u32*)smem;                 // hi frags
    const u32* wsl = wsh + WPN;                        // lo frags

    const float* relb = rel + (size_t)b * S_ * RS + (size_t)sk * D_;
    const float* myrel = relb + (size_t)(32 * w) * RS;

    // ---- prefetch chunks 0..2 (per-warp, 4 cp.async.16 per lane per chunk) ----
#pragma unroll
    for (int c = 0; c < 3; ++c) {
#pragma unroll
        for (int i = 0; i < 4; ++i) {
            int r = g + 8 * i;
            cpasync16(raw_su + (u32)(c * 3072 + r * 96 + tg * 16),
                      myrel + (size_t)r * RS + 16 * c + tg * 4);
        }
        cp_commit();
    }

    // ---- stage p_s, v_s, bias ----
    for (int i = tid; i < H_ * S_; i += 256) {
        int h = i >> 8, sq = i & 255;
        p_s[i] = g_pt[(((size_t)b * H_ + h) * S_ + sk) * S_ + sq];
    }
    for (int i = tid; i < D_; i += 256) {
        int h = i >> 6, e = i & 63;
        v_s[i] = v[(((size_t)b * H_ + h) * S_ + sk) * E_ + e];
    }
    if (tid < L_) bias_s[tid] = bias[tid];
    __syncthreads();

    // ---- stage packed W (96KB from L2) ----
    {
        const uint4* src = (const uint4*)g_wp;
        uint4* dst = (uint4*)smem;
        for (int i = tid; i < 2 * WPN / 4; i += 256) dst[i] = src[i];
    }
    // ---- cv[l][h] = sum_e W[l, 64h+e] * v[h,e] ----
    for (int task = tid; task < L_ * H_; task += 256) {
        int l = task / H_, h = task - l * H_;
        const float4* wr = (const float4*)(W + l * D_ + h * 64);
        const float4* vr = (const float4*)(v_s + h * 64);
        float s = 0.f;
#pragma unroll
        for (int e = 0; e < 16; ++e) {
            float4 a = wr[e], c = vr[e];
            s += a.x * c.x + a.y * c.y + a.z * c.z + a.w * c.w;
        }
        cv_s[task] = s;
    }
    __syncthreads();

    // ---- mainloop: no block syncs, per-warp pipeline ----
    float acc[2][4][4];
#pragma unroll
    for (int m = 0; m < 2; ++m)
#pragma unroll
        for (int nt = 0; nt < 4; ++nt)
#pragma unroll
            for (int q = 0; q < 4; ++q) acc[m][nt][q] = 0.f;

    float pvA0 = 0.f, pvB0 = 0.f, pvA1 = 0.f, pvB1 = 0.f;

    for (int c = 0; c < NCHUNK; ++c) {
        const int buf = c & 3;

        // issue chunk c+3 into buf (c+3)&3
        if (c + 3 < NCHUNK) {
            const int c3 = c + 3;
            const u32 du = raw_su + (u32)((c3 & 3) * 3072);
#pragma unroll
            for (int i = 0; i < 4; ++i) {
                int r = g + 8 * i;
                cpasync16(du + (u32)(r * 96 + tg * 16),
                          myrel + (size_t)r * RS + 16 * c3 + tg * 4);
            }
        }
        cp_commit();
        cp_wait3();     // chunk c resident

        if ((c & 3) == 0) {
            const int h = c >> 2;
            const float* pb = p_s + h * 256 + 32 * w;
            pvA0 = pb[g];      pvB0 = pb[g + 8];
            pvA1 = pb[16 + g]; pvB1 = pb[24 - 8 + g + 8];  // = pb[16+g+8]
        }

        // convert A fragments (hi/lo) for both mtiles
        u32 ah[2][4], al[2][4];
#pragma unroll
        for (int m = 0; m < 2; ++m) {
            const float* rp = rawb + buf * 768 + (16 * m) * 24;
            const float pA = m ? pvA1 : pvA0;
            const float pB = m ? pvB1 : pvB0;
            float2 f0 = *(const float2*)(rp + g * 24 + 2 * tg);
            float2 f1 = *(const float2*)(rp + (g + 8) * 24 + 2 * tg);
            float2 f2 = *(const float2*)(rp + g * 24 + 2 * tg + 8);
            float2 f3 = *(const float2*)(rp + (g + 8) * 24 + 2 * tg + 8);
            split_pair(f0.x * pA, f0.y * pA, ah[m][0], al[m][0]);
            split_pair(f1.x * pB, f1.y * pB, ah[m][1], al[m][1]);
            split_pair(f2.x * pA, f2.y * pA, ah[m][2], al[m][2]);
            split_pair(f3.x * pB, f3.y * pB, ah[m][3], al[m][3]);
        }

        // MMAs: 4 ntiles x (2 mtiles x 3 split terms)
#pragma unroll
        for (int nt = 0; nt < 4; ++nt) {
            const int bi = (c * 32 + nt * 8 + g) * 8 + tg * 2;
            u64 bhp = *(const u64*)(wsh + bi);
            u64 blp = *(const u64*)(wsl + bi);
            u32 bh0 = (u32)bhp, bh1 = (u32)(bhp >> 32);
            u32 bl0 = (u32)blp, bl1 = (u32)(blp >> 32);
#pragma unroll
            for (int m = 0; m < 2; ++m) {
                mma_bf16(acc[m][nt], ah[m], bh0, bh1);
                mma_bf16(acc[m][nt], al[m], bh0, bh1);
                mma_bf16(acc[m][nt], ah[m], bl0, bl1);
            }
        }
    }

    // ---- epilogue: bias + v-correction + store ----
    float* ob = out + ((size_t)(b * S_ + sk) * L_) * S_;
#pragma unroll
    for (int m = 0; m < 2; ++m) {
#pragma unroll
        for (int i = 0; i < 2; ++i) {
            const int row = 32 * w + 16 * m + g + 8 * i;
            float pr[H_];
#pragma unroll
            for (int h = 0; h < H_; ++h) pr[h] = p_s[h * 256 + row];
#pragma unroll
            for (int nt = 0; nt < 4; ++nt) {
#pragma unroll
                for (int j = 0; j < 2; ++j) {
                    const int l = 8 * nt + 2 * tg + j;
                    if (l < L_) {
                        float val = acc[m][nt][2 * i + j] + bias_s[l];
#pragma unroll
                        for (int h = 0; h < H_; ++h)
                            val += pr[h] * cv_s[l * H_ + h];
                        ob[(size_t)l * S_ + row] = val;
                    }
                }
            }
        }
    }
}

extern "C" void kernel_launch(void* const* d_in, const int* in_sizes, int n_in,
                              void* d_out, int out_size) {
    const float* p    = (const float*)d_in[0];
    const float* v    = (const float*)d_in[1];
    const float* rel  = (const float*)d_in[2];
    const float* W    = (const float*)d_in[3];
    const float* bias = (const float*)d_in[4];
    float* out = (float*)d_out;

    dim3 gt(S_ / 32, S_ / 32, B_ * H_);
    transpose_p_kernel<<<gt, dim3(32, 8)>>>(p);
    pack_w_kernel<<<24, 256>>>(W);

    const int smem_bytes = SMEM_FLOATS * (int)sizeof(float);  // 213312
    cudaFuncSetAttribute(mhs_mma_kernel,
                         cudaFuncAttributeMaxDynamicSharedMemorySize, smem_bytes);
    mhs_mma_kernel<<<B_ * S_, 256, smem_bytes>>>(v, rel, W, bias, out);
}